// round 1
// baseline (speedup 1.0000x reference)
#include <cuda_runtime.h>
#include <math.h>

// ---------------------------------------------------------------------------
// Problem constants
// ---------------------------------------------------------------------------
#define BWIN   1024            // B_ : number of windows
#define BIMG   64              // B  : number of images
#define NTOK   49              // tokens per window
#define CH     512             // channels
#define NH     16              // heads
#define HD     32              // head dim
#define MTOT   (BWIN * NTOK)   // 50176 rows

// Scratch (allocation-free rule: __device__ globals)
__device__ float g_kv[(size_t)MTOT * 1024];  // kv projection output [50176, 1024]
__device__ float g_x [(size_t)MTOT * CH];    // attention output     [50176, 512]

// ---------------------------------------------------------------------------
// SGEMM: C[M,N] = A[M,K] @ B[K,N] + bias[N]
// 128x128 tile, BK=8, 256 threads, 8x8 microtile (4+4 split for LDS.128)
// Requires M%128==0, N%128==0, K%8==0 (true for all launches here).
// ---------------------------------------------------------------------------
__global__ void __launch_bounds__(256, 2) sgemm_bias_kernel(
    const float* __restrict__ A, const float* __restrict__ Bm,
    const float* __restrict__ bias, float* __restrict__ C,
    int M, int N, int K)
{
    __shared__ float As[8][128];
    __shared__ float Bs[8][128];

    const int tid = threadIdx.x;
    const int tr  = tid >> 4;          // 0..15
    const int tc  = tid & 15;          // 0..15
    const int bM  = blockIdx.y * 128;
    const int bN  = blockIdx.x * 128;

    // load mapping
    const int aRow = tid >> 1;         // 0..127
    const int aCol = (tid & 1) * 4;    // 0 or 4
    const int bRow = tid >> 5;         // 0..7
    const int bCol = (tid & 31) * 4;   // 0..124

    const float* Ap = A  + (size_t)(bM + aRow) * K + aCol;
    const float* Bp = Bm + bN + bCol;

    float acc[8][8];
    #pragma unroll
    for (int i = 0; i < 8; i++)
        #pragma unroll
        for (int j = 0; j < 8; j++) acc[i][j] = 0.f;

    for (int k0 = 0; k0 < K; k0 += 8) {
        float4 av = *(const float4*)(Ap + k0);
        As[aCol + 0][aRow] = av.x;
        As[aCol + 1][aRow] = av.y;
        As[aCol + 2][aRow] = av.z;
        As[aCol + 3][aRow] = av.w;
        float4 bv = *(const float4*)(Bp + (size_t)(k0 + bRow) * N);
        *(float4*)&Bs[bRow][bCol] = bv;
        __syncthreads();

        #pragma unroll
        for (int kk = 0; kk < 8; kk++) {
            float ra[8], rb[8];
            *(float4*)&ra[0] = *(const float4*)&As[kk][tr * 4];
            *(float4*)&ra[4] = *(const float4*)&As[kk][64 + tr * 4];
            *(float4*)&rb[0] = *(const float4*)&Bs[kk][tc * 4];
            *(float4*)&rb[4] = *(const float4*)&Bs[kk][64 + tc * 4];
            #pragma unroll
            for (int i = 0; i < 8; i++)
                #pragma unroll
                for (int j = 0; j < 8; j++)
                    acc[i][j] += ra[i] * rb[j];
        }
        __syncthreads();
    }

    #pragma unroll
    for (int i = 0; i < 8; i++) {
        int row = bM + ((i < 4) ? (tr * 4 + i) : (64 + tr * 4 + (i - 4)));
        #pragma unroll
        for (int jq = 0; jq < 2; jq++) {
            int col = bN + jq * 64 + tc * 4;
            float4 o;
            o.x = acc[i][jq * 4 + 0] + bias[col + 0];
            o.y = acc[i][jq * 4 + 1] + bias[col + 1];
            o.z = acc[i][jq * 4 + 2] + bias[col + 2];
            o.w = acc[i][jq * 4 + 3] + bias[col + 3];
            *(float4*)(C + (size_t)row * N + col) = o;
        }
    }
}

// ---------------------------------------------------------------------------
// Attention: one block per (window, head). 16384 blocks x 128 threads.
// q (scaled), k, v in smem (+1 pad to avoid 32-stride bank conflicts),
// 49x49 scores + relative-position bias, softmax, attn @ v.
// ---------------------------------------------------------------------------
__global__ void __launch_bounds__(128) attn_kernel(
    const float* __restrict__ q_global,
    const float* __restrict__ bias_table)
{
    const int bh = blockIdx.x;
    const int b_ = bh >> 4;      // window index
    const int h  = bh & 15;      // head index
    const int b  = b_ >> 4;      // image index (B_/B = 16 windows per image)
    const int tid = threadIdx.x;

    __shared__ float qs[NTOK][HD + 1];
    __shared__ float ks[NTOK][HD + 1];
    __shared__ float vs[NTOK][HD + 1];
    __shared__ float sc[NTOK][NTOK];

    const float scale = 0.17677669529663687f;  // 32^-0.5

    // load q/k/v tiles (32-float contiguous chunks -> coalesced)
    for (int t = tid; t < NTOK * HD; t += 128) {
        int n = t >> 5, d = t & 31;
        qs[n][d] = q_global[((size_t)b * NTOK + n) * CH + h * HD + d] * scale;
        size_t kvrow = ((size_t)(b_ * NTOK + n)) * 1024 + h * HD + d;
        ks[n][d] = g_kv[kvrow];
        vs[n][d] = g_kv[kvrow + CH];
    }
    __syncthreads();

    // scores + bias
    for (int p = tid; p < NTOK * NTOK; p += 128) {
        int i = p / NTOK, j = p - i * NTOK;
        float a = 0.f;
        #pragma unroll
        for (int d = 0; d < HD; d++) a += qs[i][d] * ks[j][d];
        int ih = i / 7, iw = i - ih * 7;
        int jh = j / 7, jw = j - jh * 7;
        int idx = (ih - jh + 6) * 13 + (iw - jw + 6);
        a += bias_table[idx * NH + h];
        sc[i][j] = a;
    }
    __syncthreads();

    // softmax (one row per thread, 49 active)
    if (tid < NTOK) {
        int i = tid;
        float m = -1e30f;
        #pragma unroll 7
        for (int j = 0; j < NTOK; j++) m = fmaxf(m, sc[i][j]);
        float s = 0.f;
        #pragma unroll 7
        for (int j = 0; j < NTOK; j++) { float e = __expf(sc[i][j] - m); sc[i][j] = e; s += e; }
        float inv = 1.0f / s;
        #pragma unroll 7
        for (int j = 0; j < NTOK; j++) sc[i][j] *= inv;
    }
    __syncthreads();

    // x = attn @ v, written directly in [b_, n, h, d] layout for GEMM2
    for (int e = tid; e < NTOK * HD; e += 128) {
        int i = e >> 5, d = e & 31;
        float a = 0.f;
        #pragma unroll 7
        for (int j = 0; j < NTOK; j++) a += sc[i][j] * vs[j][d];
        g_x[((size_t)(b_ * NTOK + i)) * CH + h * HD + d] = a;
    }
}

// ---------------------------------------------------------------------------
// Launch
// ---------------------------------------------------------------------------
extern "C" void kernel_launch(void* const* d_in, const int* in_sizes, int n_in,
                              void* d_out, int out_size)
{
    const float* inputs     = (const float*)d_in[0];  // [1024, 49, 512]
    const float* q_global   = (const float*)d_in[1];  // [64, 49, 512]
    const float* qkv_w      = (const float*)d_in[2];  // [512, 1024]
    const float* qkv_b      = (const float*)d_in[3];  // [1024]
    const float* bias_table = (const float*)d_in[4];  // [169, 16]
    const float* proj_w     = (const float*)d_in[5];  // [512, 512]
    const float* proj_b     = (const float*)d_in[6];  // [512]
    float*       out        = (float*)d_out;          // [1024, 49, 512]

    float *kv_ptr = nullptr, *x_ptr = nullptr;
    cudaGetSymbolAddress((void**)&kv_ptr, g_kv);
    cudaGetSymbolAddress((void**)&x_ptr,  g_x);

    // 1) kv = inputs @ qkv_w + qkv_b   (M=50176, N=1024, K=512)
    {
        dim3 grid(1024 / 128, MTOT / 128);
        sgemm_bias_kernel<<<grid, 256>>>(inputs, qkv_w, qkv_b, kv_ptr,
                                         MTOT, 1024, CH);
    }

    // 2) attention per (window, head)
    attn_kernel<<<BWIN * NH, 128>>>(q_global, bias_table);

    // 3) out = x @ proj_w + proj_b   (M=50176, N=512, K=512)
    {
        dim3 grid(CH / 128, MTOT / 128);
        sgemm_bias_kernel<<<grid, 256>>>(x_ptr, proj_w, proj_b, out,
                                         MTOT, CH, CH);
    }
}

// round 3
// speedup vs baseline: 3.0074x; 3.0074x over previous
#include <cuda_runtime.h>
#include <cuda_bf16.h>
#include <cstdint>

// ---------------------------------------------------------------------------
// Problem constants
// ---------------------------------------------------------------------------
#define BWIN   1024
#define BIMG   64
#define NTOK   49
#define CH     512
#define NH     16
#define HD     32
#define MTOT   (BWIN * NTOK)     // 50176
#define KDIM   512
#define BKE    32                // K elems per stage
#define KITERS (KDIM / BKE)      // 16
#define AST    40                // smem row stride (bf16 elems) = 80 bytes
#define MAT_BYTES   (128 * AST * 2)      // 10240 per matrix (Ah/Al/Bh/Bl)
#define STAGE_BYTES (4 * MAT_BYTES)      // 40960
#define SMEM_BYTES  (2 * STAGE_BYTES)    // 81920

// ---------------------------------------------------------------------------
// Scratch (__device__ globals; allocation-free rule)
// ---------------------------------------------------------------------------
__device__ float         g_kv [(size_t)MTOT * 1024];   // kv projection (fp32)
__device__ __nv_bfloat16 g_Ah [(size_t)MTOT * KDIM];
__device__ __nv_bfloat16 g_Al [(size_t)MTOT * KDIM];
__device__ __nv_bfloat16 g_xh [(size_t)MTOT * KDIM];
__device__ __nv_bfloat16 g_xl [(size_t)MTOT * KDIM];
__device__ __nv_bfloat16 g_W1h[1024 * 512], g_W1l[1024 * 512];
__device__ __nv_bfloat16 g_W2h[ 512 * 512], g_W2l[ 512 * 512];

// ---------------------------------------------------------------------------
// Helpers
// ---------------------------------------------------------------------------
__device__ __forceinline__ uint32_t s2u(const void* p) {
    uint32_t a;
    asm("{ .reg .u64 t; cvta.to.shared.u64 t, %1; cvt.u32.u64 %0, t; }" : "=r"(a) : "l"(p));
    return a;
}

#define LDSM4(R, addr)                                                         \
    asm volatile("ldmatrix.sync.aligned.m8n8.x4.shared.b16 {%0,%1,%2,%3}, [%4];" \
                 : "=r"((R)[0]), "=r"((R)[1]), "=r"((R)[2]), "=r"((R)[3])       \
                 : "r"(addr))

#define MMA16816(Cf, Af, b0, b1)                                               \
    asm volatile("mma.sync.aligned.m16n8k16.row.col.f32.bf16.bf16.f32 "        \
                 "{%0,%1,%2,%3}, {%4,%5,%6,%7}, {%8,%9}, {%0,%1,%2,%3};"       \
                 : "+f"((Cf)[0]), "+f"((Cf)[1]), "+f"((Cf)[2]), "+f"((Cf)[3])  \
                 : "r"((Af)[0]), "r"((Af)[1]), "r"((Af)[2]), "r"((Af)[3]),     \
                   "r"(b0), "r"(b1))

// ---------------------------------------------------------------------------
// Conversion kernels
// ---------------------------------------------------------------------------
__global__ void split_kernel(const float4* __restrict__ X,
                             uint2* __restrict__ H, uint2* __restrict__ L, int n4) {
    int i = blockIdx.x * blockDim.x + threadIdx.x;
    if (i >= n4) return;
    float4 v = X[i];
    __nv_bfloat16 h0 = __float2bfloat16(v.x), h1 = __float2bfloat16(v.y);
    __nv_bfloat16 h2 = __float2bfloat16(v.z), h3 = __float2bfloat16(v.w);
    __nv_bfloat16 l0 = __float2bfloat16(v.x - __bfloat162float(h0));
    __nv_bfloat16 l1 = __float2bfloat16(v.y - __bfloat162float(h1));
    __nv_bfloat16 l2 = __float2bfloat16(v.z - __bfloat162float(h2));
    __nv_bfloat16 l3 = __float2bfloat16(v.w - __bfloat162float(h3));
    __nv_bfloat162 p01, p23, q01, q23;
    p01.x = h0; p01.y = h1; p23.x = h2; p23.y = h3;
    q01.x = l0; q01.y = l1; q23.x = l2; q23.y = l3;
    uint2 hv, lv;
    hv.x = *reinterpret_cast<unsigned*>(&p01); hv.y = *reinterpret_cast<unsigned*>(&p23);
    lv.x = *reinterpret_cast<unsigned*>(&q01); lv.y = *reinterpret_cast<unsigned*>(&q23);
    H[i] = hv; L[i] = lv;
}

// W [K,N] fp32 -> Th/Tl [N,K] bf16
__global__ void transpose_split(const float* __restrict__ W,
                                __nv_bfloat16* __restrict__ Th,
                                __nv_bfloat16* __restrict__ Tl, int K, int N) {
    __shared__ float t[32][33];
    int n0 = blockIdx.x * 32, k0 = blockIdx.y * 32;
    for (int i = threadIdx.y; i < 32; i += 8)
        t[i][threadIdx.x] = W[(size_t)(k0 + i) * N + n0 + threadIdx.x];
    __syncthreads();
    for (int i = threadIdx.y; i < 32; i += 8) {
        float v = t[threadIdx.x][i];
        __nv_bfloat16 h = __float2bfloat16(v);
        __nv_bfloat16 l = __float2bfloat16(v - __bfloat162float(h));
        Th[(size_t)(n0 + i) * K + k0 + threadIdx.x] = h;
        Tl[(size_t)(n0 + i) * K + k0 + threadIdx.x] = l;
    }
}

// ---------------------------------------------------------------------------
// mma.sync bf16 GEMM: C[M,N] = (Ah+Al)[M,K] @ (Bh+Bl)[N,K]^T + bias
// hi*hi + hi*lo + lo*hi (lo*lo dropped), fp32 accumulate.
// ---------------------------------------------------------------------------
__device__ __forceinline__ void fill_stage(uint32_t sbase,
                                           const __nv_bfloat16* const srcs[4],
                                           int k0, int tid) {
    #pragma unroll
    for (int t = 0; t < 8; t++) {
        int c   = tid + t * 256;          // 0..2047
        int mat = c >> 9;                 // 0..3
        int r   = (c >> 2) & 127;         // row 0..127
        int ch  = c & 3;                  // 16B chunk in row
        uint32_t dst = sbase + mat * MAT_BYTES + r * (AST * 2) + ch * 16;
        const char* src = (const char*)(srcs[mat] + (size_t)r * KDIM + k0) + ch * 16;
        asm volatile("cp.async.cg.shared.global [%0], [%1], 16;" :: "r"(dst), "l"(src));
    }
    asm volatile("cp.async.commit_group;" ::: "memory");
}

__global__ void __launch_bounds__(256, 1) gemm_tc(
    const __nv_bfloat16* __restrict__ Ah, const __nv_bfloat16* __restrict__ Al,
    const __nv_bfloat16* __restrict__ Bh, const __nv_bfloat16* __restrict__ Bl,
    const float* __restrict__ bias, float* __restrict__ C, int N)
{
    extern __shared__ char smem[];
    const uint32_t sb = s2u(smem);
    const int tid = threadIdx.x, wid = tid >> 5, lane = tid & 31;
    const int wm = (wid & 1) * 64;        // warp M origin within tile
    const int wn = (wid >> 1) * 32;       // warp N origin within tile
    const int bM = blockIdx.y * 128, bN = blockIdx.x * 128;

    const __nv_bfloat16* srcs[4] = {
        Ah + (size_t)bM * KDIM, Al + (size_t)bM * KDIM,
        Bh + (size_t)bN * KDIM, Bl + (size_t)bN * KDIM };

    float acc[4][4][4];
    #pragma unroll
    for (int i = 0; i < 4; i++)
        #pragma unroll
        for (int j = 0; j < 4; j++)
            #pragma unroll
            for (int e = 0; e < 4; e++) acc[i][j][e] = 0.f;

    const int lrow = lane & 15;           // ldmatrix row within 16
    const int lcolB = ((lane >> 4) << 3) * 2;  // ldmatrix k-half, bytes

    fill_stage(sb, srcs, 0, tid);

    for (int it = 0; it < KITERS; it++) {
        if (it + 1 < KITERS) {
            fill_stage(sb + ((it + 1) & 1) * STAGE_BYTES, srcs, (it + 1) * BKE, tid);
            asm volatile("cp.async.wait_group 1;" ::: "memory");
        } else {
            asm volatile("cp.async.wait_group 0;" ::: "memory");
        }
        __syncthreads();

        uint32_t st = sb + (it & 1) * STAGE_BYTES;
        #pragma unroll
        for (int ks = 0; ks < 2; ks++) {
            uint32_t kb = ks * 32 + lcolB;   // byte offset of k within stage row
            uint32_t ah[4][4], al[4][4], bh[2][4], bl[2][4];
            #pragma unroll
            for (int i = 0; i < 4; i++) {
                uint32_t ra = st + (wm + i * 16 + lrow) * (AST * 2) + kb;
                LDSM4(ah[i], ra);
                LDSM4(al[i], ra + MAT_BYTES);
            }
            #pragma unroll
            for (int j2 = 0; j2 < 2; j2++) {
                uint32_t rb = st + 2 * MAT_BYTES + (wn + j2 * 16 + lrow) * (AST * 2) + kb;
                LDSM4(bh[j2], rb);
            }
            #pragma unroll
            for (int i = 0; i < 4; i++)
                #pragma unroll
                for (int j = 0; j < 4; j++) {
                    int j2 = j >> 1, sel = j & 1;
                    MMA16816(acc[i][j], ah[i], bh[j2][sel], bh[j2][sel + 2]);
                    MMA16816(acc[i][j], al[i], bh[j2][sel], bh[j2][sel + 2]);
                }
            #pragma unroll
            for (int j2 = 0; j2 < 2; j2++) {
                uint32_t rb = st + 3 * MAT_BYTES + (wn + j2 * 16 + lrow) * (AST * 2) + kb;
                LDSM4(bl[j2], rb);
            }
            #pragma unroll
            for (int i = 0; i < 4; i++)
                #pragma unroll
                for (int j = 0; j < 4; j++) {
                    int j2 = j >> 1, sel = j & 1;
                    MMA16816(acc[i][j], ah[i], bl[j2][sel], bl[j2][sel + 2]);
                }
        }
        __syncthreads();
    }

    // epilogue: direct register store + bias
    #pragma unroll
    for (int j = 0; j < 4; j++) {
        int c0 = bN + wn + j * 8 + (lane & 3) * 2;
        float b0 = bias[c0], b1 = bias[c0 + 1];
        #pragma unroll
        for (int i = 0; i < 4; i++) {
            int r0 = bM + wm + i * 16 + (lane >> 2);
            float2 v0 = { acc[i][j][0] + b0, acc[i][j][1] + b1 };
            float2 v1 = { acc[i][j][2] + b0, acc[i][j][3] + b1 };
            *(float2*)&C[(size_t)r0 * N + c0]       = v0;
            *(float2*)&C[(size_t)(r0 + 8) * N + c0] = v1;
        }
    }
}

// ---------------------------------------------------------------------------
// Attention: one block per (window, head); writes x as bf16 hi/lo
// ---------------------------------------------------------------------------
__global__ void __launch_bounds__(128) attn_kernel(
    const float* __restrict__ q_global,
    const float* __restrict__ bias_table)
{
    const int bh = blockIdx.x;
    const int b_ = bh >> 4;
    const int h  = bh & 15;
    const int b  = b_ >> 4;
    const int tid = threadIdx.x;

    __shared__ float qs[NTOK][HD + 1];
    __shared__ float ks[NTOK][HD + 1];
    __shared__ float vs[NTOK][HD + 1];
    __shared__ float sc[NTOK][NTOK];

    const float scale = 0.17677669529663687f;

    for (int t = tid; t < NTOK * HD; t += 128) {
        int n = t >> 5, d = t & 31;
        qs[n][d] = q_global[((size_t)b * NTOK + n) * CH + h * HD + d] * scale;
        size_t kvrow = ((size_t)(b_ * NTOK + n)) * 1024 + h * HD + d;
        ks[n][d] = g_kv[kvrow];
        vs[n][d] = g_kv[kvrow + CH];
    }
    __syncthreads();

    {
        int i = tid >> 1, half = tid & 1;
        if (i < NTOK) {
            float qreg[HD];
            #pragma unroll
            for (int d = 0; d < HD; d++) qreg[d] = qs[i][d];
            int ih = i / 7, iw = i - ih * 7;
            int j0 = half ? 25 : 0, j1 = half ? NTOK : 25;
            for (int j = j0; j < j1; j++) {
                float a = 0.f;
                #pragma unroll
                for (int d = 0; d < HD; d++) a += qreg[d] * ks[j][d];
                int jh = j / 7, jw = j - jh * 7;
                int idx = (ih - jh + 6) * 13 + (iw - jw + 6);
                sc[i][j] = a + bias_table[idx * NH + h];
            }
        }
    }
    __syncthreads();

    if (tid < NTOK) {
        int i = tid;
        float m = -1e30f;
        #pragma unroll 7
        for (int j = 0; j < NTOK; j++) m = fmaxf(m, sc[i][j]);
        float s = 0.f;
        #pragma unroll 7
        for (int j = 0; j < NTOK; j++) { float e = __expf(sc[i][j] - m); sc[i][j] = e; s += e; }
        float inv = 1.0f / s;
        #pragma unroll 7
        for (int j = 0; j < NTOK; j++) sc[i][j] *= inv;
    }
    __syncthreads();

    for (int e = tid; e < NTOK * HD; e += 128) {
        int i = e >> 5, d = e & 31;
        float a = 0.f;
        #pragma unroll 7
        for (int j = 0; j < NTOK; j++) a += sc[i][j] * vs[j][d];
        size_t off = ((size_t)(b_ * NTOK + i)) * CH + h * HD + d;
        __nv_bfloat16 hh = __float2bfloat16(a);
        g_xh[off] = hh;
        g_xl[off] = __float2bfloat16(a - __bfloat162float(hh));
    }
}

// ---------------------------------------------------------------------------
// Launch
// ---------------------------------------------------------------------------
extern "C" void kernel_launch(void* const* d_in, const int* in_sizes, int n_in,
                              void* d_out, int out_size)
{
    const float* inputs     = (const float*)d_in[0];
    const float* q_global   = (const float*)d_in[1];
    const float* qkv_w      = (const float*)d_in[2];
    const float* qkv_b      = (const float*)d_in[3];
    const float* bias_table = (const float*)d_in[4];
    const float* proj_w     = (const float*)d_in[5];
    const float* proj_b     = (const float*)d_in[6];
    float*       out        = (float*)d_out;

    float *kv_ptr;
    __nv_bfloat16 *Ah, *Al, *Xh, *Xl, *W1h, *W1l, *W2h, *W2l;
    cudaGetSymbolAddress((void**)&kv_ptr, g_kv);
    cudaGetSymbolAddress((void**)&Ah,  g_Ah);
    cudaGetSymbolAddress((void**)&Al,  g_Al);
    cudaGetSymbolAddress((void**)&Xh,  g_xh);
    cudaGetSymbolAddress((void**)&Xl,  g_xl);
    cudaGetSymbolAddress((void**)&W1h, g_W1h);
    cudaGetSymbolAddress((void**)&W1l, g_W1l);
    cudaGetSymbolAddress((void**)&W2h, g_W2h);
    cudaGetSymbolAddress((void**)&W2l, g_W2l);

    cudaFuncSetAttribute(gemm_tc, cudaFuncAttributeMaxDynamicSharedMemorySize, SMEM_BYTES);

    // 0) conversions
    {
        int n4 = MTOT * KDIM / 4;
        split_kernel<<<(n4 + 255) / 256, 256>>>((const float4*)inputs, (uint2*)Ah, (uint2*)Al, n4);
        transpose_split<<<dim3(1024 / 32, 512 / 32), dim3(32, 8)>>>(qkv_w, W1h, W1l, 512, 1024);
        transpose_split<<<dim3(512 / 32, 512 / 32), dim3(32, 8)>>>(proj_w, W2h, W2l, 512, 512);
    }

    // 1) kv = inputs @ qkv_w + qkv_b   (M=50176, N=1024, K=512)
    gemm_tc<<<dim3(1024 / 128, MTOT / 128), 256, SMEM_BYTES>>>(Ah, Al, W1h, W1l, qkv_b, kv_ptr, 1024);

    // 2) attention
    attn_kernel<<<BWIN * NH, 128>>>(q_global, bias_table);

    // 3) out = x @ proj_w + proj_b   (M=50176, N=512, K=512)
    gemm_tc<<<dim3(512 / 128, MTOT / 128), 256, SMEM_BYTES>>>(Xh, Xl, W2h, W2l, proj_b, out, 512);
}

// round 5
// speedup vs baseline: 3.6120x; 1.2010x over previous
#include <cuda_runtime.h>
#include <cuda_bf16.h>
#include <cstdint>

// ---------------------------------------------------------------------------
// Problem constants
// ---------------------------------------------------------------------------
#define BWIN   1024
#define BIMG   64
#define NTOK   49
#define CH     512
#define NH     16
#define HD     32
#define MTOT   (BWIN * NTOK)     // 50176
#define KDIM   512
#define BKE    32                // K elems per stage
#define KITERS (KDIM / BKE)      // 16
#define AST    40                // smem row stride (bf16 elems) = 80 bytes
#define MAT_BYTES   (128 * AST * 2)      // 10240 per matrix (Ah/Al/Bh/Bl)
#define STAGE_BYTES (4 * MAT_BYTES)      // 40960
#define SMEM_BYTES  (2 * STAGE_BYTES)    // 81920

// ---------------------------------------------------------------------------
// Scratch (__device__ globals; allocation-free rule)
// ---------------------------------------------------------------------------
__device__ float         g_kv [(size_t)MTOT * 1024];
__device__ __nv_bfloat16 g_Ah [(size_t)MTOT * KDIM];
__device__ __nv_bfloat16 g_Al [(size_t)MTOT * KDIM];
__device__ __nv_bfloat16 g_xh [(size_t)MTOT * KDIM];
__device__ __nv_bfloat16 g_xl [(size_t)MTOT * KDIM];
__device__ __nv_bfloat16 g_W1h[1024 * 512], g_W1l[1024 * 512];
__device__ __nv_bfloat16 g_W2h[ 512 * 512], g_W2l[ 512 * 512];

// ---------------------------------------------------------------------------
// Helpers
// ---------------------------------------------------------------------------
__device__ __forceinline__ uint32_t s2u(const void* p) {
    uint32_t a;
    asm("{ .reg .u64 t; cvta.to.shared.u64 t, %1; cvt.u32.u64 %0, t; }" : "=r"(a) : "l"(p));
    return a;
}

#define LDSM4(R, addr)                                                         \
    asm volatile("ldmatrix.sync.aligned.m8n8.x4.shared.b16 {%0,%1,%2,%3}, [%4];" \
                 : "=r"((R)[0]), "=r"((R)[1]), "=r"((R)[2]), "=r"((R)[3])       \
                 : "r"(addr))

#define MMA16816(Cf, Af, b0, b1)                                               \
    asm volatile("mma.sync.aligned.m16n8k16.row.col.f32.bf16.bf16.f32 "        \
                 "{%0,%1,%2,%3}, {%4,%5,%6,%7}, {%8,%9}, {%0,%1,%2,%3};"       \
                 : "+f"((Cf)[0]), "+f"((Cf)[1]), "+f"((Cf)[2]), "+f"((Cf)[3])  \
                 : "r"((Af)[0]), "r"((Af)[1]), "r"((Af)[2]), "r"((Af)[3]),     \
                   "r"(b0), "r"(b1))

// ---------------------------------------------------------------------------
// Conversion kernels
// ---------------------------------------------------------------------------
__global__ void split_kernel(const float4* __restrict__ X,
                             uint2* __restrict__ H, uint2* __restrict__ L, int n4) {
    int i = blockIdx.x * blockDim.x + threadIdx.x;
    if (i >= n4) return;
    float4 v = X[i];
    __nv_bfloat16 h0 = __float2bfloat16(v.x), h1 = __float2bfloat16(v.y);
    __nv_bfloat16 h2 = __float2bfloat16(v.z), h3 = __float2bfloat16(v.w);
    __nv_bfloat16 l0 = __float2bfloat16(v.x - __bfloat162float(h0));
    __nv_bfloat16 l1 = __float2bfloat16(v.y - __bfloat162float(h1));
    __nv_bfloat16 l2 = __float2bfloat16(v.z - __bfloat162float(h2));
    __nv_bfloat16 l3 = __float2bfloat16(v.w - __bfloat162float(h3));
    __nv_bfloat162 p01, p23, q01, q23;
    p01.x = h0; p01.y = h1; p23.x = h2; p23.y = h3;
    q01.x = l0; q01.y = l1; q23.x = l2; q23.y = l3;
    uint2 hv, lv;
    hv.x = *reinterpret_cast<unsigned*>(&p01); hv.y = *reinterpret_cast<unsigned*>(&p23);
    lv.x = *reinterpret_cast<unsigned*>(&q01); lv.y = *reinterpret_cast<unsigned*>(&q23);
    H[i] = hv; L[i] = lv;
}

__global__ void transpose_split(const float* __restrict__ W,
                                __nv_bfloat16* __restrict__ Th,
                                __nv_bfloat16* __restrict__ Tl, int K, int N) {
    __shared__ float t[32][33];
    int n0 = blockIdx.x * 32, k0 = blockIdx.y * 32;
    for (int i = threadIdx.y; i < 32; i += 8)
        t[i][threadIdx.x] = W[(size_t)(k0 + i) * N + n0 + threadIdx.x];
    __syncthreads();
    for (int i = threadIdx.y; i < 32; i += 8) {
        float v = t[threadIdx.x][i];
        __nv_bfloat16 h = __float2bfloat16(v);
        __nv_bfloat16 l = __float2bfloat16(v - __bfloat162float(h));
        Th[(size_t)(n0 + i) * K + k0 + threadIdx.x] = h;
        Tl[(size_t)(n0 + i) * K + k0 + threadIdx.x] = l;
    }
}

// ---------------------------------------------------------------------------
// mma.sync bf16 GEMM (hi/lo split; passes separated for MMA-latency spacing)
// ---------------------------------------------------------------------------
__device__ __forceinline__ void fill_stage(uint32_t sbase,
                                           const __nv_bfloat16* const srcs[4],
                                           int k0, int tid) {
    #pragma unroll
    for (int t = 0; t < 8; t++) {
        int c   = tid + t * 256;
        int mat = c >> 9;
        int r   = (c >> 2) & 127;
        int ch  = c & 3;
        uint32_t dst = sbase + mat * MAT_BYTES + r * (AST * 2) + ch * 16;
        const char* src = (const char*)(srcs[mat] + (size_t)r * KDIM + k0) + ch * 16;
        asm volatile("cp.async.cg.shared.global [%0], [%1], 16;" :: "r"(dst), "l"(src));
    }
    asm volatile("cp.async.commit_group;" ::: "memory");
}

__global__ void __launch_bounds__(256, 2) gemm_tc(
    const __nv_bfloat16* __restrict__ Ah, const __nv_bfloat16* __restrict__ Al,
    const __nv_bfloat16* __restrict__ Bh, const __nv_bfloat16* __restrict__ Bl,
    const float* __restrict__ bias, float* __restrict__ C, int N)
{
    extern __shared__ char smem[];
    const uint32_t sb = s2u(smem);
    const int tid = threadIdx.x, wid = tid >> 5, lane = tid & 31;
    const int wm = (wid & 1) * 64;
    const int wn = (wid >> 1) * 32;
    const int bM = blockIdx.y * 128, bN = blockIdx.x * 128;

    const __nv_bfloat16* srcs[4] = {
        Ah + (size_t)bM * KDIM, Al + (size_t)bM * KDIM,
        Bh + (size_t)bN * KDIM, Bl + (size_t)bN * KDIM };

    float acc[4][4][4];
    #pragma unroll
    for (int i = 0; i < 4; i++)
        #pragma unroll
        for (int j = 0; j < 4; j++)
            #pragma unroll
            for (int e = 0; e < 4; e++) acc[i][j][e] = 0.f;

    const int lrow  = lane & 15;
    const int lcolB = ((lane >> 4) << 3) * 2;

    fill_stage(sb, srcs, 0, tid);

    for (int it = 0; it < KITERS; it++) {
        if (it + 1 < KITERS) {
            fill_stage(sb + ((it + 1) & 1) * STAGE_BYTES, srcs, (it + 1) * BKE, tid);
            asm volatile("cp.async.wait_group 1;" ::: "memory");
        } else {
            asm volatile("cp.async.wait_group 0;" ::: "memory");
        }
        __syncthreads();

        uint32_t st = sb + (it & 1) * STAGE_BYTES;
        #pragma unroll
        for (int ks = 0; ks < 2; ks++) {
            uint32_t kb = ks * 32 + lcolB;
            uint32_t ah[4][4], al[4][4], bh[2][4], bl[2][4];
            #pragma unroll
            for (int i = 0; i < 4; i++) {
                uint32_t ra = st + (wm + i * 16 + lrow) * (AST * 2) + kb;
                LDSM4(ah[i], ra);
                LDSM4(al[i], ra + MAT_BYTES);
            }
            #pragma unroll
            for (int j2 = 0; j2 < 2; j2++) {
                uint32_t rb = st + 2 * MAT_BYTES + (wn + j2 * 16 + lrow) * (AST * 2) + kb;
                LDSM4(bh[j2], rb);
            }
            // pass 1: hi*hi — 16 independent MMAs
            #pragma unroll
            for (int i = 0; i < 4; i++)
                #pragma unroll
                for (int j = 0; j < 4; j++) {
                    int j2 = j >> 1, sel = j & 1;
                    MMA16816(acc[i][j], ah[i], bh[j2][sel], bh[j2][sel + 2]);
                }
            // pass 2: lo*hi — same-acc reuse spaced 16 MMAs apart
            #pragma unroll
            for (int i = 0; i < 4; i++)
                #pragma unroll
                for (int j = 0; j < 4; j++) {
                    int j2 = j >> 1, sel = j & 1;
                    MMA16816(acc[i][j], al[i], bh[j2][sel], bh[j2][sel + 2]);
                }
            #pragma unroll
            for (int j2 = 0; j2 < 2; j2++) {
                uint32_t rb = st + 3 * MAT_BYTES + (wn + j2 * 16 + lrow) * (AST * 2) + kb;
                LDSM4(bl[j2], rb);
            }
            // pass 3: hi*lo
            #pragma unroll
            for (int i = 0; i < 4; i++)
                #pragma unroll
                for (int j = 0; j < 4; j++) {
                    int j2 = j >> 1, sel = j & 1;
                    MMA16816(acc[i][j], ah[i], bl[j2][sel], bl[j2][sel + 2]);
                }
        }
        __syncthreads();
    }

    #pragma unroll
    for (int j = 0; j < 4; j++) {
        int c0 = bN + wn + j * 8 + (lane & 3) * 2;
        float b0 = bias[c0], b1 = bias[c0 + 1];
        #pragma unroll
        for (int i = 0; i < 4; i++) {
            int r0 = bM + wm + i * 16 + (lane >> 2);
            float2 v0 = { acc[i][j][0] + b0, acc[i][j][1] + b1 };
            float2 v1 = { acc[i][j][2] + b0, acc[i][j][3] + b1 };
            *(float2*)&C[(size_t)r0 * N + c0]       = v0;
            *(float2*)&C[(size_t)(r0 + 8) * N + c0] = v1;
        }
    }
}

// ---------------------------------------------------------------------------
// Attention v2: float4 smem, register-cached q rows, smem bias, vector AV
// ---------------------------------------------------------------------------
__global__ void __launch_bounds__(128) attn_kernel(
    const float* __restrict__ q_global,
    const float* __restrict__ bias_table)
{
    const int bh = blockIdx.x;
    const int b_ = bh >> 4;
    const int h  = bh & 15;
    const int b  = b_ >> 4;
    const int tid = threadIdx.x;

    __shared__ __align__(16) float qs[NTOK][HD];
    __shared__ __align__(16) float ks[NTOK][HD];
    __shared__ __align__(16) float vs[NTOK][HD];
    __shared__ __align__(16) float sc[NTOK][52];
    __shared__ float bias_s[169];

    const float scale = 0.17677669529663687f;

    // ---- load q/k/v (float4) + bias column for this head ----
    {
        const float4* qg = (const float4*)(q_global + ((size_t)b  * NTOK) * CH + h * HD);
        const float4* kg = (const float4*)(g_kv     + ((size_t)b_ * NTOK) * 1024 + h * HD);
        for (int t = tid; t < NTOK * 8; t += 128) {
            int n = t >> 3, c = t & 7;
            float4 qv = qg[(size_t)n * (CH / 4) + c];
            qv.x *= scale; qv.y *= scale; qv.z *= scale; qv.w *= scale;
            ((float4*)qs[n])[c] = qv;
            ((float4*)ks[n])[c] = kg[(size_t)n * 256 + c];
            ((float4*)vs[n])[c] = kg[(size_t)n * 256 + 128 + c];
        }
        for (int t = tid; t < 169; t += 128) bias_s[t] = bias_table[t * NH + h];
    }
    __syncthreads();

    // ---- scores: thread = (row i, half of j range); q in registers ----
    {
        int i = tid >> 1, half = tid & 1;
        if (i < NTOK) {
            float4 q0 = ((const float4*)qs[i])[0], q1 = ((const float4*)qs[i])[1];
            float4 q2 = ((const float4*)qs[i])[2], q3 = ((const float4*)qs[i])[3];
            float4 q4 = ((const float4*)qs[i])[4], q5 = ((const float4*)qs[i])[5];
            float4 q6 = ((const float4*)qs[i])[6], q7 = ((const float4*)qs[i])[7];
            int ih = i / 7, iw = i - ih * 7;
            int j0 = half ? 25 : 0, j1 = half ? NTOK : 25;
            for (int j = j0; j < j1; j++) {
                const float4* kr = (const float4*)ks[j];
                float4 k0 = kr[0], k1 = kr[1], k2 = kr[2], k3 = kr[3];
                float4 k4 = kr[4], k5 = kr[5], k6 = kr[6], k7 = kr[7];
                float a =
                    q0.x*k0.x + q0.y*k0.y + q0.z*k0.z + q0.w*k0.w +
                    q1.x*k1.x + q1.y*k1.y + q1.z*k1.z + q1.w*k1.w +
                    q2.x*k2.x + q2.y*k2.y + q2.z*k2.z + q2.w*k2.w +
                    q3.x*k3.x + q3.y*k3.y + q3.z*k3.z + q3.w*k3.w +
                    q4.x*k4.x + q4.y*k4.y + q4.z*k4.z + q4.w*k4.w +
                    q5.x*k5.x + q5.y*k5.y + q5.z*k5.z + q5.w*k5.w +
                    q6.x*k6.x + q6.y*k6.y + q6.z*k6.z + q6.w*k6.w +
                    q7.x*k7.x + q7.y*k7.y + q7.z*k7.z + q7.w*k7.w;
                int jh = j / 7, jw = j - jh * 7;
                int idx = (ih - jh + 6) * 13 + (iw - jw + 6);
                sc[i][j] = a + bias_s[idx];
            }
        }
    }
    __syncthreads();

    // ---- softmax (vectorized row scan) ----
    if (tid < NTOK) {
        float4* srow = (float4*)sc[tid];
        float m = sc[tid][48];
        #pragma unroll
        for (int c = 0; c < 12; c++) {
            float4 v = srow[c];
            m = fmaxf(m, fmaxf(fmaxf(v.x, v.y), fmaxf(v.z, v.w)));
        }
        float s = 0.f;
        #pragma unroll
        for (int c = 0; c < 12; c++) {
            float4 v = srow[c];
            v.x = __expf(v.x - m); v.y = __expf(v.y - m);
            v.z = __expf(v.z - m); v.w = __expf(v.w - m);
            s += v.x + v.y + v.z + v.w;
            srow[c] = v;
        }
        float e48 = __expf(sc[tid][48] - m);
        s += e48;
        float inv = 1.0f / s;
        #pragma unroll
        for (int c = 0; c < 12; c++) {
            float4 v = srow[c];
            v.x *= inv; v.y *= inv; v.z *= inv; v.w *= inv;
            srow[c] = v;
        }
        sc[tid][48] = e48 * inv;
    }
    __syncthreads();

    // ---- x = attn @ v : task = (i, d4), float4 accumulate ----
    for (int t = tid; t < NTOK * 8; t += 128) {
        int i = t >> 3, d4 = t & 7;
        float4 a = {0.f, 0.f, 0.f, 0.f};
        #pragma unroll 7
        for (int j = 0; j < NTOK; j++) {
            float w = sc[i][j];
            float4 vv = ((const float4*)vs[j])[d4];
            a.x += w * vv.x; a.y += w * vv.y; a.z += w * vv.z; a.w += w * vv.w;
        }
        size_t off = ((size_t)(b_ * NTOK + i)) * CH + h * HD + d4 * 4;
        __nv_bfloat16 h0 = __float2bfloat16(a.x), h1 = __float2bfloat16(a.y);
        __nv_bfloat16 h2 = __float2bfloat16(a.z), h3 = __float2bfloat16(a.w);
        __nv_bfloat16 l0 = __float2bfloat16(a.x - __bfloat162float(h0));
        __nv_bfloat16 l1 = __float2bfloat16(a.y - __bfloat162float(h1));
        __nv_bfloat16 l2 = __float2bfloat16(a.z - __bfloat162float(h2));
        __nv_bfloat16 l3 = __float2bfloat16(a.w - __bfloat162float(h3));
        __nv_bfloat162 ph0, ph1, pl0, pl1;
        ph0.x = h0; ph0.y = h1; ph1.x = h2; ph1.y = h3;
        pl0.x = l0; pl0.y = l1; pl1.x = l2; pl1.y = l3;
        uint2 hv, lv;
        hv.x = *reinterpret_cast<unsigned*>(&ph0); hv.y = *reinterpret_cast<unsigned*>(&ph1);
        lv.x = *reinterpret_cast<unsigned*>(&pl0); lv.y = *reinterpret_cast<unsigned*>(&pl1);
        *(uint2*)(g_xh + off) = hv;
        *(uint2*)(g_xl + off) = lv;
    }
}

// ---------------------------------------------------------------------------
// Launch
// ---------------------------------------------------------------------------
extern "C" void kernel_launch(void* const* d_in, const int* in_sizes, int n_in,
                              void* d_out, int out_size)
{
    const float* inputs     = (const float*)d_in[0];
    const float* q_global   = (const float*)d_in[1];
    const float* qkv_w      = (const float*)d_in[2];
    const float* qkv_b      = (const float*)d_in[3];
    const float* bias_table = (const float*)d_in[4];
    const float* proj_w     = (const float*)d_in[5];
    const float* proj_b     = (const float*)d_in[6];
    float*       out        = (float*)d_out;

    float *kv_ptr;
    __nv_bfloat16 *Ah, *Al, *Xh, *Xl, *W1h, *W1l, *W2h, *W2l;
    cudaGetSymbolAddress((void**)&kv_ptr, g_kv);
    cudaGetSymbolAddress((void**)&Ah,  g_Ah);
    cudaGetSymbolAddress((void**)&Al,  g_Al);
    cudaGetSymbolAddress((void**)&Xh,  g_xh);
    cudaGetSymbolAddress((void**)&Xl,  g_xl);
    cudaGetSymbolAddress((void**)&W1h, g_W1h);
    cudaGetSymbolAddress((void**)&W1l, g_W1l);
    cudaGetSymbolAddress((void**)&W2h, g_W2h);
    cudaGetSymbolAddress((void**)&W2l, g_W2l);

    cudaFuncSetAttribute(gemm_tc, cudaFuncAttributeMaxDynamicSharedMemorySize, SMEM_BYTES);

    {
        int n4 = MTOT * KDIM / 4;
        split_kernel<<<(n4 + 255) / 256, 256>>>((const float4*)inputs, (uint2*)Ah, (uint2*)Al, n4);
        transpose_split<<<dim3(1024 / 32, 512 / 32), dim3(32, 8)>>>(qkv_w, W1h, W1l, 512, 1024);
        transpose_split<<<dim3(512 / 32, 512 / 32), dim3(32, 8)>>>(proj_w, W2h, W2l, 512, 512);
    }

    gemm_tc<<<dim3(1024 / 128, MTOT / 128), 256, SMEM_BYTES>>>(Ah, Al, W1h, W1l, qkv_b, kv_ptr, 1024);

    attn_kernel<<<BWIN * NH, 128>>>(q_global, bias_table);

    gemm_tc<<<dim3(512 / 128, MTOT / 128), 256, SMEM_BYTES>>>(Xh, Xl, W2h, W2l, proj_b, out, 512);
}